// round 5
// baseline (speedup 1.0000x reference)
#include <cuda_runtime.h>
#include <cuda_bf16.h>

// Problem constants
#define N_NODES 100000
#define N_EDGES 600000
#define DIM 128

#define TM 64            // rows per tile
#define THREADS 256

// Scratch for segment_sum(edge_attr, dst) -> [N_NODES, DIM]
__device__ float g_agg[(size_t)N_NODES * DIM];

// SMEM layout (floats):
//   s_in : [TM][256] = 16384 floats (aliased as s_h [TM][128] after GEMM1)
//   s_w  : [32 k-pairs][256] = 8192 floats, layout q = col*2 + k_parity
#define SMEM_FLOATS (TM * 256 + 32 * 256)
#define SMEM_BYTES (SMEM_FLOATS * 4)

// Fast exact-enough mish: v * tanh(softplus(v)) = v * n/(n+2), n = e^v*(e^v+2)
__device__ __forceinline__ float mish_f(float v) {
    float t = __expf(v);                 // underflow->0 for very negative v => mish->0 (correct limit)
    float n = t * (t + 2.0f);
    float r = v * __fdividef(n, n + 2.0f);
    return (v > 20.0f) ? v : r;          // tanh(softplus(v)) == 1 in fp32 beyond ~15; also dodges inf/inf
}

// Packed fp32x2 helpers (Blackwell FFMA2 path — ptxas never emits this from C++;
// same constraint pattern as ptx_helpers.cuh MUL_F32X2/ADD_F32X2)
__device__ __forceinline__ void fma_f32x2(unsigned long long& acc,
                                          unsigned long long a,
                                          unsigned long long b) {
    asm("fma.rn.f32x2 %0, %1, %2, %0;" : "+l"(acc) : "l"(a), "l"(b));
}
__device__ __forceinline__ void unpack_f32x2(unsigned long long v, float& lo, float& hi) {
    asm("mov.b64 {%0, %1}, %2;" : "=f"(lo), "=f"(hi) : "l"(v));
}
__device__ __forceinline__ float hsum_f32x2(unsigned long long v) {
    float lo, hi; unpack_f32x2(v, lo, hi); return lo + hi;
}

// Stage a 64-k x 128-col weight chunk into s_w with k-pair interleave:
//   s_w[kp*256 + c*2 + p] = W[kbase + 2*kp + p][c]
__device__ __forceinline__ void stage_w(float* s_w, const float* __restrict__ W,
                                        int kbase, int tid) {
    for (int i = tid; i < 2048; i += THREADS) {
        int kp = i >> 6, q4 = i & 63;
        int c0 = q4 * 2;
        float2 w0 = *(const float2*)&W[(kbase + 2 * kp + 0) * 128 + c0];
        float2 w1 = *(const float2*)&W[(kbase + 2 * kp + 1) * 128 + c0];
        *(float4*)&s_w[kp * 256 + q4 * 4] = make_float4(w0.x, w1.x, w0.y, w1.y);
    }
}

// Two-layer MLP on a [TM,256] input tile in s_in (row stride 256).
// h = mish(in @ W1 + b1) [TM,128]; out = h @ W2 + b2 [TM,128].
// Thread (tx,ty): rows {ty, ty+8, ..., ty+56}; cols {tx*2, tx*2+1, 64+tx*2, 64+tx*2+1}.
// Accumulators are f32x2 (even-k partial, odd-k partial); folded lo+hi at epilogue.
__device__ __forceinline__ void mlp_tile(
    float* s_in, float* s_w,
    const float* __restrict__ W1, const float* __restrict__ b1,
    const float* __restrict__ W2, const float* __restrict__ b2,
    float* __restrict__ out, long long rowbase, int nvalid, int tid)
{
    const int tx = tid & 31;
    const int ty = tid >> 5;

    unsigned long long acc[8][4];
#pragma unroll
    for (int r = 0; r < 8; ++r)
#pragma unroll
        for (int c = 0; c < 4; ++c) acc[r][c] = 0ull;

    // ---- GEMM1: [TM,256] @ W1[256,128], k chunks of 64 ----
    for (int kc = 0; kc < 4; ++kc) {
        __syncthreads();
        stage_w(s_w, W1, kc * 64, tid);
        __syncthreads();
#pragma unroll 4
        for (int kp = 0; kp < 32; ++kp) {
            // weight k-pairs for this thread's 4 cols: two conflict-free LDS.128
            ulonglong2 wlo = *(const ulonglong2*)&s_w[kp * 256 + tx * 4];        // cols tx*2, tx*2+1
            ulonglong2 whi = *(const ulonglong2*)&s_w[kp * 256 + 128 + tx * 4];  // cols 64+tx*2, ...
#pragma unroll
            for (int r = 0; r < 8; ++r) {
                unsigned long long a2 =                                           // broadcast LDS.64
                    *(const unsigned long long*)&s_in[(ty + r * 8) * 256 + kc * 64 + kp * 2];
                fma_f32x2(acc[r][0], a2, wlo.x);
                fma_f32x2(acc[r][1], a2, wlo.y);
                fma_f32x2(acc[r][2], a2, whi.x);
                fma_f32x2(acc[r][3], a2, whi.y);
            }
        }
    }

    // s_in dead -> reuse as s_h [TM][128]
    __syncthreads();
    float* s_h = s_in;
    float2 b1lo = *(const float2*)&b1[tx * 2];
    float2 b1hi = *(const float2*)&b1[64 + tx * 2];
#pragma unroll
    for (int r = 0; r < 8; ++r) {
        int row = ty + r * 8;
        float2 vlo = make_float2(mish_f(hsum_f32x2(acc[r][0]) + b1lo.x),
                                 mish_f(hsum_f32x2(acc[r][1]) + b1lo.y));
        float2 vhi = make_float2(mish_f(hsum_f32x2(acc[r][2]) + b1hi.x),
                                 mish_f(hsum_f32x2(acc[r][3]) + b1hi.y));
        *(float2*)&s_h[row * 128 + tx * 2] = vlo;
        *(float2*)&s_h[row * 128 + 64 + tx * 2] = vhi;
    }

    unsigned long long acc2[8][4];
#pragma unroll
    for (int r = 0; r < 8; ++r)
#pragma unroll
        for (int c = 0; c < 4; ++c) acc2[r][c] = 0ull;

    // ---- GEMM2: [TM,128] @ W2[128,128], k chunks of 64 ----
    for (int kc = 0; kc < 2; ++kc) {
        __syncthreads();
        stage_w(s_w, W2, kc * 64, tid);
        __syncthreads();
#pragma unroll 4
        for (int kp = 0; kp < 32; ++kp) {
            ulonglong2 wlo = *(const ulonglong2*)&s_w[kp * 256 + tx * 4];
            ulonglong2 whi = *(const ulonglong2*)&s_w[kp * 256 + 128 + tx * 4];
#pragma unroll
            for (int r = 0; r < 8; ++r) {
                unsigned long long a2 =
                    *(const unsigned long long*)&s_h[(ty + r * 8) * 128 + kc * 64 + kp * 2];
                fma_f32x2(acc2[r][0], a2, wlo.x);
                fma_f32x2(acc2[r][1], a2, wlo.y);
                fma_f32x2(acc2[r][2], a2, whi.x);
                fma_f32x2(acc2[r][3], a2, whi.y);
            }
        }
    }

    float2 b2lo = *(const float2*)&b2[tx * 2];
    float2 b2hi = *(const float2*)&b2[64 + tx * 2];
#pragma unroll
    for (int r = 0; r < 8; ++r) {
        int row = ty + r * 8;
        if (row < nvalid) {
            float2 vlo = make_float2(hsum_f32x2(acc2[r][0]) + b2lo.x,
                                     hsum_f32x2(acc2[r][1]) + b2lo.y);
            float2 vhi = make_float2(hsum_f32x2(acc2[r][2]) + b2hi.x,
                                     hsum_f32x2(acc2[r][3]) + b2hi.y);
            *(float2*)&out[(rowbase + row) * 128 + tx * 2] = vlo;
            *(float2*)&out[(rowbase + row) * 128 + 64 + tx * 2] = vhi;
        }
    }
}

// ---------------- Edge kernel: e = MLP([edge_attr, x[src]+x[dst]]) + scatter agg ----------------
__global__ __launch_bounds__(THREADS, 2)
void edge_kernel(const float* __restrict__ x, const float* __restrict__ ea,
                 const int* __restrict__ eidx,
                 const float* __restrict__ W1, const float* __restrict__ b1,
                 const float* __restrict__ W2, const float* __restrict__ b2,
                 float* __restrict__ e_out, float* __restrict__ agg)
{
    extern __shared__ float sm[];
    float* s_in = sm;                 // [TM][256]
    float* s_w  = sm + TM * 256;      // [32][256] k-pair interleaved
    __shared__ int s_src[TM], s_dst[TM];

    const int tid = threadIdx.x;
    const long long base = (long long)blockIdx.x * TM;   // N_EDGES % TM == 0

    if (tid < TM) {
        long long e = base + tid;
        s_src[tid] = eidx[e];                    // int32 (JAX x64 disabled)
        s_dst[tid] = eidx[N_EDGES + e];
    }
    __syncthreads();

    // Load input tile: [edge_attr | x[src]+x[dst]]
    for (int i = tid; i < TM * 64; i += THREADS) {        // TM rows x 64 float4
        int row = i >> 6, c4 = i & 63;
        long long e = base + row;
        float4 v;
        if (c4 < 32) {
            v = *(const float4*)&ea[e * 128 + c4 * 4];
        } else {
            int c = (c4 - 32) * 4;
            float4 a = *(const float4*)&x[(long long)s_src[row] * 128 + c];
            float4 b = *(const float4*)&x[(long long)s_dst[row] * 128 + c];
            v = make_float4(a.x + b.x, a.y + b.y, a.z + b.z, a.w + b.w);
        }
        *(float4*)&s_in[row * 256 + c4 * 4] = v;
    }
    __syncthreads();

    // Scatter-add edge_attr into agg[dst] — vector atomics (sm_90+ intrinsic),
    // 2048 RED.128 per tile instead of 8192 scalar REDs.
    for (int i = tid; i < TM * 32; i += THREADS) {
        int row = i >> 5, c4 = i & 31;
        float4 v = *(const float4*)&s_in[row * 256 + c4 * 4];
        (void)atomicAdd((float4*)&agg[(long long)s_dst[row] * 128 + c4 * 4], v);
    }

    mlp_tile(s_in, s_w, W1, b1, W2, b2, e_out, base, TM, tid);
}

// ---------------- Node kernel: x_out = MLP([x, agg]) ----------------
__global__ __launch_bounds__(THREADS, 2)
void node_kernel(const float* __restrict__ x, const float* __restrict__ agg,
                 const float* __restrict__ W1, const float* __restrict__ b1,
                 const float* __restrict__ W2, const float* __restrict__ b2,
                 float* __restrict__ x_out)
{
    extern __shared__ float sm[];
    float* s_in = sm;
    float* s_w  = sm + TM * 256;

    const int tid = threadIdx.x;
    const long long base = (long long)blockIdx.x * TM;
    const int nvalid = (int)min((long long)TM, (long long)N_NODES - base);

    for (int i = tid; i < TM * 64; i += THREADS) {
        int row = i >> 6, c4 = i & 63;
        float4 v = make_float4(0.f, 0.f, 0.f, 0.f);
        if (row < nvalid) {
            long long n = base + row;
            if (c4 < 32) v = *(const float4*)&x[n * 128 + c4 * 4];
            else         v = *(const float4*)&agg[n * 128 + (c4 - 32) * 4];
        }
        *(float4*)&s_in[row * 256 + c4 * 4] = v;
    }
    // visibility of s_in handled by the first __syncthreads inside mlp_tile

    mlp_tile(s_in, s_w, W1, b1, W2, b2, x_out, base, nvalid, tid);
}

extern "C" void kernel_launch(void* const* d_in, const int* in_sizes, int n_in,
                              void* d_out, int out_size)
{
    const float* x    = (const float*)d_in[0];
    const float* ea   = (const float*)d_in[1];
    const int*   eidx = (const int*)d_in[2];      // int32: JAX default has x64 disabled
    const float* eW1  = (const float*)d_in[3];
    const float* eb1  = (const float*)d_in[4];
    const float* eW2  = (const float*)d_in[5];
    const float* eb2  = (const float*)d_in[6];
    const float* nW1  = (const float*)d_in[7];
    const float* nb1  = (const float*)d_in[8];
    const float* nW2  = (const float*)d_in[9];
    const float* nb2  = (const float*)d_in[10];

    float* out   = (float*)d_out;
    float* x_out = out;                                 // [N_NODES,128] first (tuple order)
    float* e_out = out + (long long)N_NODES * DIM;      // then e [N_EDGES,128]

    void* aggp = nullptr;
    cudaGetSymbolAddress(&aggp, g_agg);
    cudaMemsetAsync(aggp, 0, sizeof(float) * (size_t)N_NODES * DIM);

    cudaFuncSetAttribute(edge_kernel, cudaFuncAttributeMaxDynamicSharedMemorySize, SMEM_BYTES);
    cudaFuncSetAttribute(node_kernel, cudaFuncAttributeMaxDynamicSharedMemorySize, SMEM_BYTES);

    int edge_blocks = N_EDGES / TM;                     // 9375
    int node_blocks = (N_NODES + TM - 1) / TM;          // 1563

    edge_kernel<<<edge_blocks, THREADS, SMEM_BYTES>>>(
        x, ea, eidx, eW1, eb1, eW2, eb2, e_out, (float*)aggp);
    node_kernel<<<node_blocks, THREADS, SMEM_BYTES>>>(
        x, (const float*)aggp, nW1, nb1, nW2, nb2, x_out);
}